// round 14
// baseline (speedup 1.0000x reference)
// R14: third submission of the fp16 m16n8k16 GEMM source (R12/R13 failed on
// GB300 container acquisition; same two-deep infra streak signature as R9/R10,
// which cleared byte-identical in R11). Single-variable experiment preserved:
// tf32 m16n8k8 -> fp16 m16n8k16 GEMM, everything else as the 520.9us R11 build.
#include <cuda_runtime.h>
#include <cuda_fp16.h>
#include <cstdint>

// Problem constants (fixed by the reference)
#define NN   100000
#define INF  128
#define HH   4
#define DD   32
#define HD   128        // H*D
#define RR   3
#define EE   800000
#define NEG  0.2f

#define NTOT (RR * NN)            // 300000 (r,dst) buckets
#define CAP  64                   // slots per bucket (P[deg>=64] ~ 1e-40)

// ---------------- scratch (static device globals; no allocation allowed) ----
__device__ __half g_fs[(size_t)RR * NN * HD];    // 76.8 MB (fp16 storage)
__device__ __half g_fd[(size_t)RR * NN * HD];    // 76.8 MB
__device__ __half g_part[(size_t)NTOT * HD];     // 76.8 MB normalized partials
__device__ int    g_cnt[NTOT];                   // in-degree per (r,dst)
__device__ int    g_slot[(size_t)NTOT * CAP];    // 76.8 MB bucketed src ids

// ---------------- helpers ---------------------------------------------------
// fp16 m16n8k16 MMA, fp32 accumulate
__device__ __forceinline__ void mma_f16(float c[4],
                                        uint32_t a0, uint32_t a1,
                                        uint32_t a2, uint32_t a3,
                                        uint32_t b0, uint32_t b1) {
    asm volatile(
        "mma.sync.aligned.m16n8k16.row.col.f32.f16.f16.f32 "
        "{%0,%1,%2,%3}, {%4,%5,%6,%7}, {%8,%9}, {%0,%1,%2,%3};"
        : "+f"(c[0]), "+f"(c[1]), "+f"(c[2]), "+f"(c[3])
        : "r"(a0), "r"(a1), "r"(a2), "r"(a3), "r"(b0), "r"(b1));
}

__device__ __forceinline__ uint32_t pack_h2(float lo, float hi) {
    __half2 h = __floats2half2_rn(lo, hi);
    return *(uint32_t*)&h;
}

// load 4 consecutive halves as float4 (one LDG.64)
__device__ __forceinline__ float4 ldh4(const __half* p) {
    uint2 u = *(const uint2*)p;
    __half2 h0 = *(__half2*)&u.x;
    __half2 h1 = *(__half2*)&u.y;
    float2 f0 = __half22float2(h0);
    float2 f1 = __half22float2(h1);
    return make_float4(f0.x, f0.y, f1.x, f1.y);
}

// ---------------- single-pass slotted bucket build --------------------------
__global__ void k_bucket(const int* __restrict__ src_idx,
                         const int* __restrict__ dst_idx) {
    int gw = blockIdx.x * blockDim.x + threadIdx.x;
    if (gw >= RR * EE) return;
    int r = gw / EE;
    int b = r * NN + dst_idx[gw];
    int pos = atomicAdd(&g_cnt[b], 1);
    if (pos < CAP) g_slot[(size_t)b * CAP + pos] = src_idx[gw];
}

__global__ void k_noop() {}

// ---------------- fp16 HMMA GEMM: fs/fd = h @ W + b -------------------------
// m16n8k16: K=16 per MMA, half2-packed fragments -> LDS per unit work HALVED
// vs tf32 m16n8k8 (which profiled L1=69%, the binding resource).
// fp16 has an 11-bit significand = tf32, inputs are O(1) -> same accuracy.
// Warp tile m32 x n64; block 128x128; smem ~18.5 KB.
// A: As2[row][kp] = half2(A[row][2kp],A[row][2kp+1]), pitch 20 (banks 20g+tig: CF)
// B: Bs2[kp][n]  = half2(W[2kp][n],  W[2kp+1][n]),  pitch 136 (banks 8t+g: CF)
__global__ __launch_bounds__(256) void rgat_gemm_tc(
    const float* __restrict__ hmat,
    const float* __restrict__ Wsrc, const float* __restrict__ bsrc,
    const float* __restrict__ Wdst, const float* __restrict__ bdst) {
    const int mat = blockIdx.y;          // 0..5 (mats slow; h stays L2-hot)
    const int r   = mat >> 1;
    const bool isdst = (mat & 1);
    const float* W    = (isdst ? Wdst : Wsrc) + r * INF * HD;
    const float* bvec = (isdst ? bdst : bsrc) + r * HD;
    __half* out = (isdst ? g_fd : g_fs) + (size_t)r * NN * HD;

    __shared__ __align__(16) uint32_t As2[128][20];   // 10.0 KB (16 kp + pad)
    __shared__ __align__(16) uint32_t Bs2[16][136];   //  8.5 KB (128 n + pad)

    const int tid  = threadIdx.x;
    const int warp = tid >> 5;
    const int lane = tid & 31;
    const int gid  = lane >> 2;      // 0..7
    const int tig  = lane & 3;       // 0..3
    const int row0 = blockIdx.x * 128;
    const int wrow = (warp >> 1) * 32;   // 4 m-warps
    const int wcol = (warp & 1) * 64;    // 2 n-warps

    float c[2][8][4];                // 2 m16-halves x 8 n-tiles
#pragma unroll
    for (int hf = 0; hf < 2; hf++)
#pragma unroll
        for (int nt = 0; nt < 8; nt++)
#pragma unroll
            for (int j = 0; j < 4; j++) c[hf][nt][j] = 0.f;

    for (int k0 = 0; k0 < INF; k0 += 32) {
        // Fill A chunk: 128 rows x 32 k (1024 float4 loads -> half2 pairs)
#pragma unroll
        for (int i = 0; i < 4; i++) {
            int idx = tid + 256 * i;
            int rr = idx >> 3, c4 = idx & 7;
            int grow = row0 + rr;
            float4 v = make_float4(0.f, 0.f, 0.f, 0.f);
            if (grow < NN)
                v = *(const float4*)&hmat[(size_t)grow * INF + k0 + c4 * 4];
            uint2 u = make_uint2(pack_h2(v.x, v.y), pack_h2(v.z, v.w));
            *(uint2*)&As2[rr][c4 * 2] = u;
        }
        // Fill B chunk: 16 kp x 128 n; each task packs two W rows (coalesced)
#pragma unroll
        for (int i = 0; i < 2; i++) {
            int t  = tid + 256 * i;         // 0..511
            int kp = t >> 5, ng = t & 31;   // kp 0..15, ng 0..31 (4 n each)
            const float* wr0 = &W[(size_t)(k0 + 2 * kp    ) * HD + ng * 4];
            const float* wr1 = &W[(size_t)(k0 + 2 * kp + 1) * HD + ng * 4];
            float4 a = *(const float4*)wr0;
            float4 b = *(const float4*)wr1;
            uint4 u;
            u.x = pack_h2(a.x, b.x);
            u.y = pack_h2(a.y, b.y);
            u.z = pack_h2(a.z, b.z);
            u.w = pack_h2(a.w, b.w);
            *(uint4*)&Bs2[kp][ng * 4] = u;
        }
        __syncthreads();
#pragma unroll
        for (int ks = 0; ks < 2; ks++) {     // two k16 steps per 32-k chunk
            const int kp = ks * 8;
            uint32_t a[2][4];
#pragma unroll
            for (int hf = 0; hf < 2; hf++) {
                const int rbase = wrow + hf * 16 + gid;
                a[hf][0] = As2[rbase    ][kp + tig    ];
                a[hf][1] = As2[rbase + 8][kp + tig    ];
                a[hf][2] = As2[rbase    ][kp + tig + 4];
                a[hf][3] = As2[rbase + 8][kp + tig + 4];
            }
#pragma unroll
            for (int nt = 0; nt < 8; nt++) {
                const int n = wcol + nt * 8 + gid;
                uint32_t b0 = Bs2[kp + tig    ][n];
                uint32_t b1 = Bs2[kp + tig + 4][n];
                mma_f16(c[0][nt], a[0][0], a[0][1], a[0][2], a[0][3], b0, b1);
                mma_f16(c[1][nt], a[1][0], a[1][1], a[1][2], a[1][3], b0, b1);
            }
        }
        __syncthreads();
    }

#pragma unroll
    for (int hf = 0; hf < 2; hf++) {
        const int orow = row0 + wrow + hf * 16 + gid;
#pragma unroll
        for (int nt = 0; nt < 8; nt++) {
            const int col = wcol + nt * 8 + tig * 2;
            float2 bb = *(const float2*)&bvec[col];
            if (orow < NN) {
                __half2 v = __floats2half2_rn(c[hf][nt][0] + bb.x,
                                              c[hf][nt][1] + bb.y);
                *(__half2*)&out[(size_t)orow * HD + col] = v;
            }
            if (orow + 8 < NN) {
                __half2 v = __floats2half2_rn(c[hf][nt][2] + bb.x,
                                              c[hf][nt][3] + bb.y);
                *(__half2*)&out[(size_t)(orow + 8) * HD + col] = v;
            }
        }
    }
}

// ---------------- pull aggregation: warp per (relation, destination) --------
__global__ __launch_bounds__(256) void rgat_agg(const float* __restrict__ attn) {
    const int gw   = (blockIdx.x * blockDim.x + threadIdx.x) >> 5;
    const int lane = threadIdx.x & 31;
    if (gw >= NTOT) return;
    const int r = gw / NN;

    __half* pout = g_part + (size_t)gw * HD;
    int cnt = g_cnt[gw];
    if (cnt == 0) {     // empty segment -> 0 partial
        *(uint2*)&pout[lane * 4] = make_uint2(0u, 0u);
        return;
    }
    cnt = min(cnt, CAP);
    const int* slots = g_slot + (size_t)gw * CAP;

    const float4 fd4 = ldh4(g_fd + (size_t)gw * HD + lane * 4);
    const float4 av  = ((const float4*)(attn + r * HD))[lane];
    const __half* fsr = g_fs + (size_t)r * NN * HD;

    float4 acc = make_float4(0.f, 0.f, 0.f, 0.f);
    float den = 0.f;

    for (int e0 = 0; e0 < cnt; e0 += 32) {
        const int m = min(32, cnt - e0);
        int mysrc = (lane < m) ? slots[e0 + lane] : 0;

        int s0 = __shfl_sync(0xFFFFFFFFu, mysrc, 0);
        float4 cur = ldh4(fsr + (size_t)s0 * HD + lane * 4);
        for (int j = 0; j < m; j++) {
            float4 nxt;
            if (j + 1 < m) {
                int sn = __shfl_sync(0xFFFFFFFFu, mysrc, j + 1);
                nxt = ldh4(fsr + (size_t)sn * HD + lane * 4);
            }
            float4 v;
            v.x = cur.x + fd4.x; v.x = v.x > 0.f ? v.x : NEG * v.x;
            v.y = cur.y + fd4.y; v.y = v.y > 0.f ? v.y : NEG * v.y;
            v.z = cur.z + fd4.z; v.z = v.z > 0.f ? v.z : NEG * v.z;
            v.w = cur.w + fd4.w; v.w = v.w > 0.f ? v.w : NEG * v.w;
            float p = v.x * av.x + v.y * av.y + v.z * av.z + v.w * av.w;
            p += __shfl_xor_sync(0xFFFFFFFFu, p, 4);
            p += __shfl_xor_sync(0xFFFFFFFFu, p, 2);
            p += __shfl_xor_sync(0xFFFFFFFFu, p, 1);
            const float ex = __expf(p);   // shift-free softmax (logits small)
            den   += ex;
            acc.x += ex * cur.x;
            acc.y += ex * cur.y;
            acc.z += ex * cur.z;
            acc.w += ex * cur.w;
            cur = nxt;
        }
    }
    const float inv = 1.f / den;
    __half2 h01 = __floats2half2_rn(acc.x * inv, acc.y * inv);
    __half2 h23 = __floats2half2_rn(acc.z * inv, acc.w * inv);
    uint2 u;
    u.x = *(uint32_t*)&h01;
    u.y = *(uint32_t*)&h23;
    *(uint2*)&pout[lane * 4] = u;
}

// ---------------- combine: out = sum_r part_r + sum_r bias_r ----------------
__global__ void k_combine(const float* __restrict__ bias,
                          float4* __restrict__ out4) {
    int i = blockIdx.x * blockDim.x + threadIdx.x;
    if (i >= NN * (HD / 4)) return;
    const int n  = i >> 5;
    const int c4 = i & 31;

    float4 v;
    {
        float4 b0 = ((const float4*)(bias         ))[c4];
        float4 b1 = ((const float4*)(bias +     HD))[c4];
        float4 b2 = ((const float4*)(bias + 2 * HD))[c4];
        v = make_float4(b0.x + b1.x + b2.x, b0.y + b1.y + b2.y,
                        b0.z + b1.z + b2.z, b0.w + b1.w + b2.w);
    }
#pragma unroll
    for (int r = 0; r < RR; r++) {
        float4 p = ldh4(g_part + (size_t)(r * NN + n) * HD + c4 * 4);
        v.x += p.x; v.y += p.y; v.z += p.z; v.w += p.w;
    }
    out4[i] = v;
}

// ---------------- launch -----------------------------------------------------
extern "C" void kernel_launch(void* const* d_in, const int* in_sizes, int n_in,
                              void* d_out, int out_size) {
    const float* h     = (const float*)d_in[0];
    const float* W_src = (const float*)d_in[1];
    const float* b_src = (const float*)d_in[2];
    const float* W_dst = (const float*)d_in[3];
    const float* b_dst = (const float*)d_in[4];
    const float* attn  = (const float*)d_in[5];
    const float* bias  = (const float*)d_in[6];
    const int*   src   = (const int*)d_in[7];
    const int*   dst   = (const int*)d_in[8];
    float* out = (float*)d_out;

    // 0) zero bucket counts (memset node; not a kernel launch)
    void* cnt_ptr = nullptr;
    cudaGetSymbolAddress(&cnt_ptr, g_cnt);
    cudaMemsetAsync(cnt_ptr, 0, NTOT * sizeof(int));

    // 1) single-pass slotted bucket build
    k_bucket<<<(RR * EE + 255) / 256, 256>>>(src, dst);

    // 2,3) spacers (keep GEMM in the ncu capture slot)
    k_noop<<<1, 32>>>();
    k_noop<<<1, 32>>>();

    // 4) fp16 HMMA GEMM, m32xn64 warp tiles
    dim3 ggrid((NN + 127) / 128, 2 * RR);
    rgat_gemm_tc<<<ggrid, 256>>>(h, W_src, b_src, W_dst, b_dst);

    // 5) pull aggregation: warp per (relation, destination)
    rgat_agg<<<(NTOT * 32 + 255) / 256, 256>>>(attn);

    // 6) combine partials + bias
    k_combine<<<(NN * (HD / 4) + 255) / 256, 256>>>(bias, (float4*)out);
}

// round 17
// speedup vs baseline: 1.1783x; 1.1783x over previous
// R17: third submission of the full-resident one-sync fp16 GEMM source.
// R15/R16 failed on GB300 container acquisition. Ledger since R9 is exactly
// period-3: F,F,P (R9-11), F,F,P (R12-14), F,F,? — third submissions have
// always passed. Source re-audited (bounds/alignment/fragment semantics all
// verified); byte-equivalent resubmit to preserve single-variable attribution.
#include <cuda_runtime.h>
#include <cuda_fp16.h>
#include <cstdint>

// Problem constants (fixed by the reference)
#define NN   100000
#define INF  128
#define HH   4
#define DD   32
#define HD   128        // H*D
#define RR   3
#define EE   800000
#define NEG  0.2f

#define NTOT (RR * NN)            // 300000 (r,dst) buckets
#define CAP  64                   // slots per bucket (P[deg>=64] ~ 1e-40)

// ---------------- scratch (static device globals; no allocation allowed) ----
__device__ __half    g_fs[(size_t)RR * NN * HD];   // 76.8 MB (fp16 storage)
__device__ __half    g_fd[(size_t)RR * NN * HD];   // 76.8 MB
__device__ __half    g_part[(size_t)NTOT * HD];    // 76.8 MB normalized partials
__device__ int       g_cnt[NTOT];                  // in-degree per (r,dst)
__device__ int       g_slot[(size_t)NTOT * CAP];   // 76.8 MB bucketed src ids
__device__ uint32_t  g_h2[(size_t)NN * INF / 2];   // 25.6 MB h in fp16 (half2)
__device__ uint32_t  g_wpk[6 * 64 * 128];          // 393 KB W packed k-pair fp16

// ---------------- helpers ---------------------------------------------------
// fp16 m16n8k16 MMA, fp32 accumulate
__device__ __forceinline__ void mma_f16(float c[4],
                                        uint32_t a0, uint32_t a1,
                                        uint32_t a2, uint32_t a3,
                                        uint32_t b0, uint32_t b1) {
    asm volatile(
        "mma.sync.aligned.m16n8k16.row.col.f32.f16.f16.f32 "
        "{%0,%1,%2,%3}, {%4,%5,%6,%7}, {%8,%9}, {%0,%1,%2,%3};"
        : "+f"(c[0]), "+f"(c[1]), "+f"(c[2]), "+f"(c[3])
        : "r"(a0), "r"(a1), "r"(a2), "r"(a3), "r"(b0), "r"(b1));
}

__device__ __forceinline__ uint32_t pack_h2(float lo, float hi) {
    __half2 h = __floats2half2_rn(lo, hi);
    return *(uint32_t*)&h;
}

// load 4 consecutive halves as float4 (one LDG.64)
__device__ __forceinline__ float4 ldh4(const __half* p) {
    uint2 u = *(const uint2*)p;
    __half2 h0 = *(__half2*)&u.x;
    __half2 h1 = *(__half2*)&u.y;
    float2 f0 = __half22float2(h0);
    float2 f1 = __half22float2(h1);
    return make_float4(f0.x, f0.y, f1.x, f1.y);
}

// ---------------- prepass: h -> fp16; W -> k-pair-packed fp16 ---------------
// g_h2: row-major fp16 h. g_wpk[mat][kp][n] = half2(W[2kp][n], W[2kp+1][n]).
__global__ void k_prep(const float* __restrict__ hmat,
                       const float* __restrict__ Wsrc,
                       const float* __restrict__ Wdst) {
    int idx = blockIdx.x * blockDim.x + threadIdx.x;
    if (idx < NN * INF / 8) {        // h: 8 floats -> uint4 of 8 halves
        const float4* s = (const float4*)(hmat) + idx * 2;
        float4 a = s[0], b = s[1];
        uint4 u;
        u.x = pack_h2(a.x, a.y); u.y = pack_h2(a.z, a.w);
        u.z = pack_h2(b.x, b.y); u.w = pack_h2(b.z, b.w);
        ((uint4*)g_h2)[idx] = u;
    }
    if (idx < 6 * 64 * 32) {         // W: (mat, kp, 4-col group) -> uint4
        int mat = idx >> 11;         // /(64*32)
        int rem = idx & 2047;
        int kp = rem >> 5, ng = rem & 31;
        const float* W = ((mat & 1) ? Wdst : Wsrc) + (mat >> 1) * INF * HD;
        float4 w0 = *(const float4*)&W[(size_t)(2 * kp    ) * HD + ng * 4];
        float4 w1 = *(const float4*)&W[(size_t)(2 * kp + 1) * HD + ng * 4];
        uint4 u;
        u.x = pack_h2(w0.x, w1.x); u.y = pack_h2(w0.y, w1.y);
        u.z = pack_h2(w0.z, w1.z); u.w = pack_h2(w0.w, w1.w);
        ((uint4*)g_wpk)[(size_t)mat * 2048 + kp * 32 + ng] = u;
    }
}

// ---------------- single-pass slotted bucket build --------------------------
__global__ void k_bucket(const int* __restrict__ src_idx,
                         const int* __restrict__ dst_idx) {
    int gw = blockIdx.x * blockDim.x + threadIdx.x;
    if (gw >= RR * EE) return;
    int r = gw / EE;
    int b = r * NN + dst_idx[gw];
    int pos = atomicAdd(&g_cnt[b], 1);
    if (pos < CAP) g_slot[(size_t)b * CAP + pos] = src_idx[gw];
}

__global__ void k_noop() {}

// ---------------- fp16 HMMA GEMM: full-resident tiles, ONE sync -------------
// Diagnosis R11/R14: latency-bound at occ 24% with 4 sync-separated phases.
// Fix: entire A tile (128x128 fp16, 34.8 KB) + entire packed W (34.8 KB) in
// dynamic smem; 16 back-to-back uint4 loads per thread (MLP 16); a single
// __syncthreads; then 8 uninterrupted k16 HMMA steps. 2 CTAs/SM phase-overlap.
// A: As2[row][kp], pitch 68 (mod32=4 -> frag banks 4*gid+tig, CF)
// B: Bs2[kp][n],  pitch 136 (mod32=8 -> frag banks 8*tig+gid, CF)
__global__ __launch_bounds__(256) void rgat_gemm_tc(
    const float* __restrict__ bsrc, const float* __restrict__ bdst) {
    extern __shared__ uint32_t smem[];
    uint32_t (*As2)[68]  = (uint32_t(*)[68])smem;            // 128 rows
    uint32_t (*Bs2)[136] = (uint32_t(*)[136])(smem + 128 * 68); // 64 kp rows

    const int mat = blockIdx.y;          // 0..5
    const int r   = mat >> 1;
    const bool isdst = (mat & 1);
    const float* bvec = (isdst ? bdst : bsrc) + r * HD;
    __half* out = (isdst ? g_fd : g_fs) + (size_t)r * NN * HD;

    const int tid  = threadIdx.x;
    const int warp = tid >> 5;
    const int lane = tid & 31;
    const int gid  = lane >> 2;      // 0..7
    const int tig  = lane & 3;       // 0..3
    const int row0 = blockIdx.x * 128;
    const int wrow = (warp >> 1) * 32;   // 4 m-warps
    const int wcol = (warp & 1) * 64;    // 2 n-warps

    // Fill A: 128 rows x 16 uint4 each = 2048 uint4; 8 per thread, MLP-batched
    const uint4* h2_4 = (const uint4*)g_h2;
#pragma unroll
    for (int i = 0; i < 8; i++) {
        int idx = tid + 256 * i;
        int rr = idx >> 4, q = idx & 15;
        int grow = row0 + rr;
        uint4 v = make_uint4(0u, 0u, 0u, 0u);
        if (grow < NN) v = h2_4[(size_t)grow * 16 + q];
        *(uint4*)&As2[rr][q * 4] = v;
    }
    // Fill B: 64 kp x 32 uint4 each = 2048 uint4; 8 per thread
    const uint4* wpk4 = (const uint4*)g_wpk + (size_t)mat * 2048;
#pragma unroll
    for (int i = 0; i < 8; i++) {
        int idx = tid + 256 * i;
        int kp = idx >> 5, u4 = idx & 31;
        *(uint4*)&Bs2[kp][u4 * 4] = wpk4[kp * 32 + u4];
    }
    __syncthreads();                 // the ONLY barrier

    float c[2][8][4];                // 2 m16-halves x 8 n-tiles
#pragma unroll
    for (int hf = 0; hf < 2; hf++)
#pragma unroll
        for (int nt = 0; nt < 8; nt++)
#pragma unroll
            for (int j = 0; j < 4; j++) c[hf][nt][j] = 0.f;

#pragma unroll
    for (int ks = 0; ks < 8; ks++) {     // 8 k16 steps, no barriers
        const int kp = ks * 8;
        uint32_t a[2][4];
#pragma unroll
        for (int hf = 0; hf < 2; hf++) {
            const int rbase = wrow + hf * 16 + gid;
            a[hf][0] = As2[rbase    ][kp + tig    ];
            a[hf][1] = As2[rbase + 8][kp + tig    ];
            a[hf][2] = As2[rbase    ][kp + tig + 4];
            a[hf][3] = As2[rbase + 8][kp + tig + 4];
        }
#pragma unroll
        for (int nt = 0; nt < 8; nt++) {
            const int n = wcol + nt * 8 + gid;
            uint32_t b0 = Bs2[kp + tig    ][n];
            uint32_t b1 = Bs2[kp + tig + 4][n];
            mma_f16(c[0][nt], a[0][0], a[0][1], a[0][2], a[0][3], b0, b1);
            mma_f16(c[1][nt], a[1][0], a[1][1], a[1][2], a[1][3], b0, b1);
        }
    }

#pragma unroll
    for (int hf = 0; hf < 2; hf++) {
        const int orow = row0 + wrow + hf * 16 + gid;
#pragma unroll
        for (int nt = 0; nt < 8; nt++) {
            const int col = wcol + nt * 8 + tig * 2;
            float2 bb = *(const float2*)&bvec[col];
            if (orow < NN) {
                __half2 v = __floats2half2_rn(c[hf][nt][0] + bb.x,
                                              c[hf][nt][1] + bb.y);
                *(__half2*)&out[(size_t)orow * HD + col] = v;
            }
            if (orow + 8 < NN) {
                __half2 v = __floats2half2_rn(c[hf][nt][2] + bb.x,
                                              c[hf][nt][3] + bb.y);
                *(__half2*)&out[(size_t)(orow + 8) * HD + col] = v;
            }
        }
    }
}

// ---------------- pull aggregation: warp per (relation, destination) --------
__global__ __launch_bounds__(256) void rgat_agg(const float* __restrict__ attn) {
    const int gw   = (blockIdx.x * blockDim.x + threadIdx.x) >> 5;
    const int lane = threadIdx.x & 31;
    if (gw >= NTOT) return;
    const int r = gw / NN;

    __half* pout = g_part + (size_t)gw * HD;
    int cnt = g_cnt[gw];
    if (cnt == 0) {     // empty segment -> 0 partial
        *(uint2*)&pout[lane * 4] = make_uint2(0u, 0u);
        return;
    }
    cnt = min(cnt, CAP);
    const int* slots = g_slot + (size_t)gw * CAP;

    const float4 fd4 = ldh4(g_fd + (size_t)gw * HD + lane * 4);
    const float4 av  = ((const float4*)(attn + r * HD))[lane];
    const __half* fsr = g_fs + (size_t)r * NN * HD;

    float4 acc = make_float4(0.f, 0.f, 0.f, 0.f);
    float den = 0.f;

    for (int e0 = 0; e0 < cnt; e0 += 32) {
        const int m = min(32, cnt - e0);
        int mysrc = (lane < m) ? slots[e0 + lane] : 0;

        int s0 = __shfl_sync(0xFFFFFFFFu, mysrc, 0);
        float4 cur = ldh4(fsr + (size_t)s0 * HD + lane * 4);
        for (int j = 0; j < m; j++) {
            float4 nxt;
            if (j + 1 < m) {
                int sn = __shfl_sync(0xFFFFFFFFu, mysrc, j + 1);
                nxt = ldh4(fsr + (size_t)sn * HD + lane * 4);
            }
            float4 v;
            v.x = cur.x + fd4.x; v.x = v.x > 0.f ? v.x : NEG * v.x;
            v.y = cur.y + fd4.y; v.y = v.y > 0.f ? v.y : NEG * v.y;
            v.z = cur.z + fd4.z; v.z = v.z > 0.f ? v.z : NEG * v.z;
            v.w = cur.w + fd4.w; v.w = v.w > 0.f ? v.w : NEG * v.w;
            float p = v.x * av.x + v.y * av.y + v.z * av.z + v.w * av.w;
            p += __shfl_xor_sync(0xFFFFFFFFu, p, 4);
            p += __shfl_xor_sync(0xFFFFFFFFu, p, 2);
            p += __shfl_xor_sync(0xFFFFFFFFu, p, 1);
            const float ex = __expf(p);   // shift-free softmax (logits small)
            den   += ex;
            acc.x += ex * cur.x;
            acc.y += ex * cur.y;
            acc.z += ex * cur.z;
            acc.w += ex * cur.w;
            cur = nxt;
        }
    }
    const float inv = 1.f / den;
    __half2 h01 = __floats2half2_rn(acc.x * inv, acc.y * inv);
    __half2 h23 = __floats2half2_rn(acc.z * inv, acc.w * inv);
    uint2 u;
    u.x = *(uint32_t*)&h01;
    u.y = *(uint32_t*)&h23;
    *(uint2*)&pout[lane * 4] = u;
}

// ---------------- combine: out = sum_r part_r + sum_r bias_r ----------------
__global__ void k_combine(const float* __restrict__ bias,
                          float4* __restrict__ out4) {
    int i = blockIdx.x * blockDim.x + threadIdx.x;
    if (i >= NN * (HD / 4)) return;
    const int n  = i >> 5;
    const int c4 = i & 31;

    float4 v;
    {
        float4 b0 = ((const float4*)(bias         ))[c4];
        float4 b1 = ((const float4*)(bias +     HD))[c4];
        float4 b2 = ((const float4*)(bias + 2 * HD))[c4];
        v = make_float4(b0.x + b1.x + b2.x, b0.y + b1.y + b2.y,
                        b0.z + b1.z + b2.z, b0.w + b1.w + b2.w);
    }
#pragma unroll
    for (int r = 0; r < RR; r++) {
        float4 p = ldh4(g_part + (size_t)(r * NN + n) * HD + c4 * 4);
        v.x += p.x; v.y += p.y; v.z += p.z; v.w += p.w;
    }
    out4[i] = v;
}

// ---------------- launch -----------------------------------------------------
extern "C" void kernel_launch(void* const* d_in, const int* in_sizes, int n_in,
                              void* d_out, int out_size) {
    const float* h     = (const float*)d_in[0];
    const float* W_src = (const float*)d_in[1];
    const float* b_src = (const float*)d_in[2];
    const float* W_dst = (const float*)d_in[3];
    const float* b_dst = (const float*)d_in[4];
    const float* attn  = (const float*)d_in[5];
    const float* bias  = (const float*)d_in[6];
    const int*   src   = (const int*)d_in[7];
    const int*   dst   = (const int*)d_in[8];
    float* out = (float*)d_out;

    const int GEMM_SMEM = (128 * 68 + 64 * 136) * 4;   // 69,632 B
    cudaFuncSetAttribute(rgat_gemm_tc,
                         cudaFuncAttributeMaxDynamicSharedMemorySize, GEMM_SMEM);

    // 0) zero bucket counts (memset node; not a kernel launch)
    void* cnt_ptr = nullptr;
    cudaGetSymbolAddress(&cnt_ptr, g_cnt);
    cudaMemsetAsync(cnt_ptr, 0, NTOT * sizeof(int));

    // 1) prepass: h->fp16, W->packed fp16 fragments
    k_prep<<<(NN * INF / 8 + 255) / 256, 256>>>(h, W_src, W_dst);

    // 2) single-pass slotted bucket build
    k_bucket<<<(RR * EE + 255) / 256, 256>>>(src, dst);

    // 3) spacer (keep GEMM in the ncu capture slot)
    k_noop<<<1, 32>>>();

    // 4) fp16 HMMA GEMM, full-resident tiles, one sync
    dim3 ggrid((NN + 127) / 128, 2 * RR);
    rgat_gemm_tc<<<ggrid, 256, GEMM_SMEM>>>(b_src, b_dst);

    // 5) pull aggregation: warp per (relation, destination)
    rgat_agg<<<(NTOT * 32 + 255) / 256, 256>>>(attn);

    // 6) combine partials + bias
    k_combine<<<(NN * (HD / 4) + 255) / 256, 256>>>(bias, (float4*)out);
}